// round 16
// baseline (speedup 1.0000x reference)
#include <cuda_runtime.h>
#include <cuda_bf16.h>
#include <cuda_fp16.h>
#include <stdint.h>

#define NODES 4096
#define CDIM  256
#define NEDGE 65536
#define OUTW  1024
#define NCTA  128

// ---------------- device scratch (no allocations allowed) ----------------
__device__ __half d_A16 [NODES * CDIM];   // fp16 activations
__device__ __half d_Bh16[3 * 512 * 256];  // fp16 packed weights
__device__ __half d_Gj16[NODES * CDIM];   // Yj  = X @ Wa^T  (fp16)
__device__ float  d_Gib [NODES * CDIM];   // Yib = X @ (Wb-Wa)^T + b (fp32)
__device__ int   d_cnt   [NODES];
__device__ int   d_rowptr[NODES + 1];
__device__ int   d_cursor[NODES];
__device__ int   d_ssrc  [NEDGE];
__device__ int   g_bars[32];

// ---------------- PTX helpers (plain sm_80-class, no 'a' features) ----------------
__device__ __forceinline__ uint32_t smem_u32(const void* p) {
    uint32_t a;
    asm("{ .reg .u64 t; cvta.to.shared.u64 t, %1; cvt.u32.u64 %0, t; }" : "=r"(a) : "l"(p));
    return a;
}
#define CP16(dst, src) \
    asm volatile("cp.async.cg.shared.global [%0], [%1], 16;" :: "r"(dst), "l"(src) : "memory")
#define CP_COMMIT() asm volatile("cp.async.commit_group;" ::: "memory")

template <int N>
__device__ __forceinline__ void cp_wait_n() {
    asm volatile("cp.async.wait_group %0;" :: "n"(N) : "memory");
}

#define LDM_X4(r0, r1, r2, r3, addr) \
    asm volatile("ldmatrix.sync.aligned.m8n8.x4.shared.b16 {%0,%1,%2,%3}, [%4];" \
        : "=r"(r0), "=r"(r1), "=r"(r2), "=r"(r3) : "r"(addr))

#define MMA16816F16(c, a, b0, b1) \
    asm volatile("mma.sync.aligned.m16n8k16.row.col.f32.f16.f16.f32 " \
        "{%0,%1,%2,%3}, {%4,%5,%6,%7}, {%8,%9}, {%0,%1,%2,%3};" \
        : "+f"((c)[0]), "+f"((c)[1]), "+f"((c)[2]), "+f"((c)[3]) \
        : "r"((a)[0]), "r"((a)[1]), "r"((a)[2]), "r"((a)[3]), "r"(b0), "r"(b1))

// ---------------- global barrier (all 128 CTAs resident: 1 CTA/SM by smem) ----------------
__device__ __forceinline__ void gbar(int idx) {
    __threadfence();
    __syncthreads();
    if (threadIdx.x == 0) {
        atomicAdd(&g_bars[idx], 1);
        while (atomicAdd(&g_bars[idx], 0) < NCTA) __nanosleep(64);
        __threadfence();
    }
    __syncthreads();
}

__global__ void reset_kernel() {
    if (threadIdx.x < 32) g_bars[threadIdx.x] = 0;
}

// ---------------- GEMM tile sizes ----------------
#define NPHYS    8                        // 256 / 32
#define TILE_B   10240                    // 128 rows x 80B (one 32-k tile, padded)
#define STAGE_B  (2 * TILE_B)             // A | B = 20480
#define SMEM_TOT (NPHYS * STAGE_B)        // 163840

// ---------------- gemm phase (device function; fully-resident smem) ----------------
__device__ __forceinline__ void gemm_phase(char* smem, int layer, const float* __restrict__ bias) {
    uint32_t sbase = smem_u32(smem);
    int tid = threadIdx.x;
    int lane = tid & 31, wid = tid >> 5;
    int wm = wid >> 2, wn = wid & 3;      // 4 x 4 warp grid, 32x32 warp tile
    int n0 = (blockIdx.x & 3) * 128;      // 0..511
    int m0 = (blockIdx.x >> 2) * 128;     // 0..4095

    const __half* Bh = d_Bh16 + layer * 512 * 256;

    int lrow = tid >> 2;
    int lcq  = tid & 3;
    uint32_t lsOff = lrow * 80 + lcq * 16;

    float acc[2][4][4];
#pragma unroll
    for (int i = 0; i < 2; i++)
#pragma unroll
        for (int j = 0; j < 4; j++)
#pragma unroll
            for (int q = 0; q < 4; q++) acc[i][j][q] = 0.f;

#pragma unroll
    for (int kp = 0; kp < NPHYS; kp++) {
        int col = kp * 32;
        uint32_t sb = sbase + kp * STAGE_B + lsOff;
        size_t gA = (size_t)(m0 + lrow) * 256 + col + lcq * 8;
        size_t gB = (size_t)(n0 + lrow) * 256 + col + lcq * 8;
        CP16(sb,          d_A16 + gA);
        CP16(sb + TILE_B, Bh + gB);
        CP_COMMIT();
    }

    int arow0 = wm * 32 + (lane & 15);
    int akq   = (lane >> 4) * 8;
    int nrow0 = wn * 32 + ((lane >> 4) & 1) * 8 + (lane & 7);
    int bkq   = ((lane >> 3) & 1) * 8;

    auto compute = [&](uint32_t stg) {
#pragma unroll
        for (int kh = 0; kh < 2; kh++) {
            int k0 = kh * 16;
            uint32_t ah[2][4], bh[2][4];
#pragma unroll
            for (int mt = 0; mt < 2; mt++) {
                uint32_t ro = (arow0 + mt * 16) * 80 + (k0 + akq) * 2;
                LDM_X4(ah[mt][0], ah[mt][1], ah[mt][2], ah[mt][3], stg + ro);
            }
#pragma unroll
            for (int np = 0; np < 2; np++) {
                uint32_t ro = (nrow0 + np * 16) * 80 + (k0 + bkq) * 2;
                LDM_X4(bh[np][0], bh[np][1], bh[np][2], bh[np][3], stg + TILE_B + ro);
            }
#pragma unroll
            for (int mt = 0; mt < 2; mt++)
#pragma unroll
                for (int nf = 0; nf < 4; nf++) {
                    int np = nf >> 1, q = (nf & 1) * 2;
                    MMA16816F16(acc[mt][nf], ah[mt], bh[np][q], bh[np][q + 1]);
                }
        }
    };

    cp_wait_n<7>(); __syncthreads(); compute(sbase + 0 * STAGE_B);
    cp_wait_n<6>(); __syncthreads(); compute(sbase + 1 * STAGE_B);
    cp_wait_n<5>(); __syncthreads(); compute(sbase + 2 * STAGE_B);
    cp_wait_n<4>(); __syncthreads(); compute(sbase + 3 * STAGE_B);
    cp_wait_n<3>(); __syncthreads(); compute(sbase + 4 * STAGE_B);
    cp_wait_n<2>(); __syncthreads(); compute(sbase + 5 * STAGE_B);
    cp_wait_n<1>(); __syncthreads(); compute(sbase + 6 * STAGE_B);
    cp_wait_n<0>(); __syncthreads(); compute(sbase + 7 * STAGE_B);

    bool isGib = (n0 >= 256);
    int g  = lane >> 2;
    int t2 = (lane & 3) * 2;
    if (isGib) {
        int ncol0 = n0 - 256 + wn * 32;
#pragma unroll
        for (int mt = 0; mt < 2; mt++) {
#pragma unroll
            for (int nf = 0; nf < 4; nf++) {
                int row = m0 + wm * 32 + mt * 16 + g;
                int col = ncol0 + nf * 8 + t2;
                float2 bb = *reinterpret_cast<const float2*>(&bias[col]);
                float2 v0 = make_float2(acc[mt][nf][0] + bb.x, acc[mt][nf][1] + bb.y);
                float2 v1 = make_float2(acc[mt][nf][2] + bb.x, acc[mt][nf][3] + bb.y);
                *reinterpret_cast<float2*>(&d_Gib[(size_t)row * 256 + col]) = v0;
                *reinterpret_cast<float2*>(&d_Gib[(size_t)(row + 8) * 256 + col]) = v1;
            }
        }
    } else {
        int ncol0 = n0 + wn * 32;
#pragma unroll
        for (int mt = 0; mt < 2; mt++) {
#pragma unroll
            for (int nf = 0; nf < 4; nf++) {
                int row = m0 + wm * 32 + mt * 16 + g;
                int col = ncol0 + nf * 8 + t2;
                __half2 h0 = __floats2half2_rn(acc[mt][nf][0], acc[mt][nf][1]);
                __half2 h1 = __floats2half2_rn(acc[mt][nf][2], acc[mt][nf][3]);
                *reinterpret_cast<__half2*>(&d_Gj16[(size_t)row * 256 + col]) = h0;
                *reinterpret_cast<__half2*>(&d_Gj16[(size_t)(row + 8) * 256 + col]) = h1;
            }
        }
    }
}

// ---------------- edge phase (device function; 32 nodes per CTA) ----------------
__device__ __forceinline__ void edge_phase(float* __restrict__ out, int layerOff, int writeNext) {
    int t  = threadIdx.x & 127;           // half2 lane within node
    int sub = threadIdx.x >> 7;           // 4 nodes in parallel
#pragma unroll
    for (int i = 0; i < 8; i++) {
        int n = blockIdx.x * 32 + i * 4 + sub;
        int beg = d_rowptr[n], end = d_rowptr[n + 1];
        const __half ninf = __ushort_as_half((unsigned short)0xFC00);
        __half2 acc0 = __half2half2(ninf);
        __half2 acc1 = acc0;
        int e = beg;
        for (; e + 2 <= end; e += 2) {
            int s0 = __ldg(&d_ssrc[e]);
            int s1 = __ldg(&d_ssrc[e + 1]);
            __half2 v0 = *reinterpret_cast<const __half2*>(&d_Gj16[(size_t)s0 * 256 + t * 2]);
            __half2 v1 = *reinterpret_cast<const __half2*>(&d_Gj16[(size_t)s1 * 256 + t * 2]);
            acc0 = __hmax2(acc0, v0);
            acc1 = __hmax2(acc1, v1);
        }
        if (e < end) {
            int s = __ldg(&d_ssrc[e]);
            __half2 v = *reinterpret_cast<const __half2*>(&d_Gj16[(size_t)s * 256 + t * 2]);
            acc0 = __hmax2(acc0, v);
        }
        float2 g = __half22float2(__hmax2(acc0, acc1));
        float2 gib = *reinterpret_cast<const float2*>(&d_Gib[(size_t)n * 256 + t * 2]);
        float r0 = fmaxf(g.x + gib.x, 0.f);   // empty segment: -inf -> relu -> 0
        float r1 = fmaxf(g.y + gib.y, 0.f);
        *reinterpret_cast<float2*>(&out[(size_t)n * OUTW + layerOff + t * 2]) = make_float2(r0, r1);
        if (writeNext) {
            __half2 h01 = __floats2half2_rn(r0, r1);
            reinterpret_cast<uint32_t*>(d_A16)[n * 128 + t] = *reinterpret_cast<uint32_t*>(&h01);
        }
    }
}

// ---------------- persistent mega-kernel ----------------
__global__ void __launch_bounds__(512, 1)
mega_kernel(const float* __restrict__ x, const int* __restrict__ ei,
            const float* __restrict__ W1, const float* __restrict__ b1,
            const float* __restrict__ W2, const float* __restrict__ b2,
            const float* __restrict__ W3, const float* __restrict__ b3,
            float* __restrict__ out) {
    extern __shared__ char smem[];
    int tid = threadIdx.x;
    int gid = blockIdx.x * 512 + tid;     // 0..65535

    const int* src = ei;
    const int* dst = ei + NEDGE;

    // ---- P0: zero cnt + copyx/conv + prep_w ----
    if (gid < NODES) d_cnt[gid] = 0;
#pragma unroll
    for (int i = 0; i < 4; i++) {         // copyx: 262144 float4 items
        int idx = gid + i * 65536;
        int n  = idx >> 6;
        int c4 = idx & 63;
        float4 v = reinterpret_cast<const float4*>(x)[n * 64 + c4];
        reinterpret_cast<float4*>(out + (size_t)n * OUTW)[c4] = v;
        __half2 h01 = __floats2half2_rn(v.x, v.y);
        __half2 h23 = __floats2half2_rn(v.z, v.w);
        uint2 hv;
        hv.x = *reinterpret_cast<uint32_t*>(&h01);
        hv.y = *reinterpret_cast<uint32_t*>(&h23);
        *reinterpret_cast<uint2*>(&d_A16[n * 256 + c4 * 4]) = hv;
    }
#pragma unroll
    for (int i = 0; i < 6; i++) {         // prep_w: 393216 elems
        int idx = gid + i * 65536;
        int l = idx / (512 * 256);
        int r = idx % (512 * 256);
        int o = r >> 8;
        int c = r & 255;
        const float* W = (l == 0) ? W1 : ((l == 1) ? W2 : W3);
        float v;
        if (o < 256) v = W[o * 512 + c];
        else {
            int oo = o - 256;
            v = W[oo * 512 + 256 + c] - W[oo * 512 + c];
        }
        d_Bh16[idx] = __float2half_rn(v);
    }
    gbar(0);

    // ---- P1: histogram of dst ----
    atomicAdd(&d_cnt[dst[gid]], 1);
    gbar(1);

    // ---- P2: exclusive scan (CTA 0 only; 512 threads x 8 elems) ----
    if (blockIdx.x == 0) {
        int* ws = reinterpret_cast<int*>(smem);   // 16 warp sums
        int lane = tid & 31, w = tid >> 5;
        int base = tid * 8;
        int v[8];
        int tsum = 0;
#pragma unroll
        for (int i = 0; i < 8; i++) { v[i] = d_cnt[base + i]; tsum += v[i]; }
        int xs = tsum;
#pragma unroll
        for (int off = 1; off < 32; off <<= 1) {
            int y = __shfl_up_sync(0xffffffffu, xs, off);
            if (lane >= off) xs += y;
        }
        if (lane == 31) ws[w] = xs;
        __syncthreads();
        if (w == 0) {
            int s = (lane < 16) ? ws[lane] : 0;
#pragma unroll
            for (int off = 1; off < 16; off <<= 1) {
                int y = __shfl_up_sync(0xffffffffu, s, off);
                if (lane >= off) s += y;
            }
            if (lane < 16) ws[lane] = s;
        }
        __syncthreads();
        int excl = xs - tsum + (w ? ws[w - 1] : 0);
        int run = excl;
#pragma unroll
        for (int i = 0; i < 8; i++) {
            d_rowptr[base + i] = run;
            d_cursor[base + i] = run;
            run += v[i];
        }
        if (tid == 511) d_rowptr[NODES] = run;
    }
    gbar(2);

    // ---- P3: scatter + gemm layer 0 ----
    {
        int d = dst[gid];
        int pos = atomicAdd(&d_cursor[d], 1);
        d_ssrc[pos] = src[gid];
    }
    gemm_phase(smem, 0, b1);
    gbar(3);

    // ---- P4: edge 0 ----
    edge_phase(out, 256, 1);
    gbar(4);

    // ---- P5: gemm 1 ----
    gemm_phase(smem, 1, b2);
    gbar(5);

    // ---- P6: edge 1 ----
    edge_phase(out, 512, 1);
    gbar(6);

    // ---- P7: gemm 2 ----
    gemm_phase(smem, 2, b3);
    gbar(7);

    // ---- P8: edge 2 ----
    edge_phase(out, 768, 0);
}

// ---------------- launch ----------------
extern "C" void kernel_launch(void* const* d_in, const int* in_sizes, int n_in,
                              void* d_out, int out_size) {
    const float* x  = (const float*)d_in[0];
    const int*   ei = (const int*)  d_in[1];
    const float* W1 = (const float*)d_in[2];
    const float* b1 = (const float*)d_in[3];
    const float* W2 = (const float*)d_in[4];
    const float* b2 = (const float*)d_in[5];
    const float* W3 = (const float*)d_in[6];
    const float* b3 = (const float*)d_in[7];
    float* out = (float*)d_out;

    static int inited = 0;
    if (!inited) {
        cudaFuncSetAttribute(mega_kernel, cudaFuncAttributeMaxDynamicSharedMemorySize, SMEM_TOT);
        inited = 1;
    }

    reset_kernel<<<1, 32>>>();
    mega_kernel<<<NCTA, 512, SMEM_TOT>>>(x, ei, W1, b1, W2, b2, W3, b3, out);
}

// round 17
// speedup vs baseline: 1.6309x; 1.6309x over previous
#include <cuda_runtime.h>
#include <cuda_bf16.h>
#include <cuda_fp16.h>
#include <stdint.h>

#define NODES 4096
#define CDIM  256
#define NEDGE 65536
#define OUTW  1024

// ---------------- device scratch (no allocations allowed) ----------------
__device__ __half d_A16 [NODES * CDIM];   // fp16 activations
__device__ __half d_Bh16[3 * 512 * 256];  // fp16 packed weights
__device__ __half d_Gj16[NODES * CDIM];   // Yj  = X @ Wa^T  (fp16)
__device__ float  d_Gib [NODES * CDIM];   // Yib = X @ (Wb-Wa)^T + b (fp32)
__device__ int   d_cnt   [NODES];
__device__ int   d_rowptr[NODES + 1];
__device__ int   d_cursor[NODES];
__device__ int   d_ssrc  [NEDGE];

// ---------------- PTX helpers (plain sm_80-class, no 'a' features) ----------------
__device__ __forceinline__ uint32_t smem_u32(const void* p) {
    uint32_t a;
    asm("{ .reg .u64 t; cvta.to.shared.u64 t, %1; cvt.u32.u64 %0, t; }" : "=r"(a) : "l"(p));
    return a;
}
#define CP16(dst, src) \
    asm volatile("cp.async.cg.shared.global [%0], [%1], 16;" :: "r"(dst), "l"(src) : "memory")
#define CP_COMMIT() asm volatile("cp.async.commit_group;" ::: "memory")
#define CP_WAIT1()  asm volatile("cp.async.wait_group 1;" ::: "memory")

#define LDM_X4(r0, r1, r2, r3, addr) \
    asm volatile("ldmatrix.sync.aligned.m8n8.x4.shared.b16 {%0,%1,%2,%3}, [%4];" \
        : "=r"(r0), "=r"(r1), "=r"(r2), "=r"(r3) : "r"(addr))

#define MMA16816F16(c, a, b0, b1) \
    asm volatile("mma.sync.aligned.m16n8k16.row.col.f32.f16.f16.f32 " \
        "{%0,%1,%2,%3}, {%4,%5,%6,%7}, {%8,%9}, {%0,%1,%2,%3};" \
        : "+f"((c)[0]), "+f"((c)[1]), "+f"((c)[2]), "+f"((c)[3]) \
        : "r"((a)[0]), "r"((a)[1]), "r"((a)[2]), "r"((a)[3]), "r"(b0), "r"(b1))

// ---------------- merged setup: copyx/conv + prep_w + hist ----------------
// d_cnt must be zeroed before launch (memset node). 256 blocks x 256 threads.
__global__ void setup_kernel(const float* __restrict__ x, float* __restrict__ out,
                             const float* __restrict__ W1, const float* __restrict__ W2,
                             const float* __restrict__ W3, const int* __restrict__ dst) {
    int gid = blockIdx.x * 256 + threadIdx.x;  // 0..65535
    // copyx + fp16 convert (262144 float4 items)
#pragma unroll
    for (int i = 0; i < 4; i++) {
        int idx = gid + i * 65536;
        int n  = idx >> 6;
        int c4 = idx & 63;
        float4 v = reinterpret_cast<const float4*>(x)[n * 64 + c4];
        reinterpret_cast<float4*>(out + (size_t)n * OUTW)[c4] = v;
        __half2 h01 = __floats2half2_rn(v.x, v.y);
        __half2 h23 = __floats2half2_rn(v.z, v.w);
        uint2 hv;
        hv.x = *reinterpret_cast<uint32_t*>(&h01);
        hv.y = *reinterpret_cast<uint32_t*>(&h23);
        *reinterpret_cast<uint2*>(&d_A16[n * 256 + c4 * 4]) = hv;
    }
    // weight prep (393216 elems)
#pragma unroll
    for (int i = 0; i < 6; i++) {
        int idx = gid + i * 65536;
        int l = idx / (512 * 256);
        int r = idx % (512 * 256);
        int o = r >> 8;
        int c = r & 255;
        const float* W = (l == 0) ? W1 : ((l == 1) ? W2 : W3);
        float v;
        if (o < 256) v = W[o * 512 + c];
        else {
            int oo = o - 256;
            v = W[oo * 512 + 256 + c] - W[oo * 512 + c];
        }
        d_Bh16[idx] = __float2half_rn(v);
    }
    // histogram (one edge per thread)
    atomicAdd(&d_cnt[dst[gid]], 1);
}

// ---------------- CSR scan + scatter ----------------
__global__ void scan_kernel() {
    __shared__ int ws[32];
    int tid = threadIdx.x, lane = tid & 31, w = tid >> 5;
    int base = tid * 4;
    int v0 = d_cnt[base], v1 = d_cnt[base + 1], v2 = d_cnt[base + 2], v3 = d_cnt[base + 3];
    int tsum = v0 + v1 + v2 + v3;
    int x = tsum;
#pragma unroll
    for (int off = 1; off < 32; off <<= 1) {
        int y = __shfl_up_sync(0xffffffffu, x, off);
        if (lane >= off) x += y;
    }
    if (lane == 31) ws[w] = x;
    __syncthreads();
    if (w == 0) {
        int s = ws[lane];
#pragma unroll
        for (int off = 1; off < 32; off <<= 1) {
            int y = __shfl_up_sync(0xffffffffu, s, off);
            if (lane >= off) s += y;
        }
        ws[lane] = s;
    }
    __syncthreads();
    int excl = x - tsum + (w ? ws[w - 1] : 0);
    int run = excl;
    d_rowptr[base]     = run; d_cursor[base]     = run; run += v0;
    d_rowptr[base + 1] = run; d_cursor[base + 1] = run; run += v1;
    d_rowptr[base + 2] = run; d_cursor[base + 2] = run; run += v2;
    d_rowptr[base + 3] = run; d_cursor[base + 3] = run; run += v3;
    if (tid == 1023) d_rowptr[NODES] = run;
}
__global__ void scatter_kernel(const int* __restrict__ src, const int* __restrict__ dst) {
    int e = blockIdx.x * 256 + threadIdx.x;
    int d = dst[e];
    int pos = atomicAdd(&d_cursor[d], 1);
    d_ssrc[pos] = src[e];
}

// ---------------- mma.sync fp16 GEMM: single term, 3-stage ring (R14 proven) ----------------
// Y[4096][512] = A16[4096x256] * Bh[512x256]^T
// BM=128 BN=128, 8 phys k-chunks, 3 stages, 512 threads (16 warps 4x4), warp tile 32x32.
#define NPHYS    8                        // 256 / 32
#define STAGES   3
#define TILE_B   10240                    // 128 rows x 80B (one 32-k tile, padded)
#define STAGE_B  (2 * TILE_B)             // A | B = 20480
#define SMEM_TOT (STAGES * STAGE_B)       // 61440

__global__ void __launch_bounds__(512, 1)
gemm_mma_kernel(int layer, const float* __restrict__ bias) {
    extern __shared__ char smem[];
    uint32_t sbase = smem_u32(smem);
    int tid = threadIdx.x;
    int lane = tid & 31, wid = tid >> 5;
    int wm = wid >> 2, wn = wid & 3;      // 4 x 4 warp grid, 32x32 warp tile
    int n0 = blockIdx.x * 128;            // 0..511
    int m0 = blockIdx.y * 128;

    const __half* Bh = d_Bh16 + layer * 512 * 256;

    int lrow = tid >> 2;                  // 0..127
    int lcq  = tid & 3;                   // 16B quarter of a 64B row
    uint32_t lsOff = lrow * 80 + lcq * 16;

    float acc[2][4][4];
#pragma unroll
    for (int i = 0; i < 2; i++)
#pragma unroll
        for (int j = 0; j < 4; j++)
#pragma unroll
            for (int q = 0; q < 4; q++) acc[i][j][q] = 0.f;

    auto load_stage = [&](int kp, int slot) {
        int col = kp * 32;
        uint32_t sb = sbase + slot * STAGE_B + lsOff;
        size_t gA = (size_t)(m0 + lrow) * 256 + col + lcq * 8;
        size_t gB = (size_t)(n0 + lrow) * 256 + col + lcq * 8;
        CP16(sb,          d_A16 + gA);
        CP16(sb + TILE_B, Bh + gB);
    };

#pragma unroll
    for (int s = 0; s < STAGES - 1; s++) {
        load_stage(s, s);
        CP_COMMIT();
    }

    int arow0 = wm * 32 + (lane & 15);
    int akq   = (lane >> 4) * 8;
    int nrow0 = wn * 32 + ((lane >> 4) & 1) * 8 + (lane & 7);
    int bkq   = ((lane >> 3) & 1) * 8;

    for (int kp = 0; kp < NPHYS; kp++) {
        CP_WAIT1();
        __syncthreads();                  // slot (kp-1) safe to overwrite
        int pf = kp + STAGES - 1;
        if (pf < NPHYS) load_stage(pf, pf % STAGES);
        CP_COMMIT();

        uint32_t stg = sbase + (kp % STAGES) * STAGE_B;

#pragma unroll
        for (int kh = 0; kh < 2; kh++) {
            int k0 = kh * 16;
            uint32_t ah[2][4], bh[2][4];
#pragma unroll
            for (int mt = 0; mt < 2; mt++) {
                uint32_t ro = (arow0 + mt * 16) * 80 + (k0 + akq) * 2;
                LDM_X4(ah[mt][0], ah[mt][1], ah[mt][2], ah[mt][3], stg + ro);
            }
#pragma unroll
            for (int np = 0; np < 2; np++) {
                uint32_t ro = (nrow0 + np * 16) * 80 + (k0 + bkq) * 2;
                LDM_X4(bh[np][0], bh[np][1], bh[np][2], bh[np][3], stg + TILE_B + ro);
            }
#pragma unroll
            for (int mt = 0; mt < 2; mt++)
#pragma unroll
                for (int nf = 0; nf < 4; nf++) {
                    int np = nf >> 1, q = (nf & 1) * 2;
                    MMA16816F16(acc[mt][nf], ah[mt], bh[np][q], bh[np][q + 1]);
                }
        }
    }

    // ---- epilogue: warp tile 32x32 ----
    bool isGib = (n0 >= 256);
    int g  = lane >> 2;
    int t2 = (lane & 3) * 2;
    if (isGib) {
        int ncol0 = n0 - 256 + wn * 32;
#pragma unroll
        for (int mt = 0; mt < 2; mt++) {
#pragma unroll
            for (int nf = 0; nf < 4; nf++) {
                int row = m0 + wm * 32 + mt * 16 + g;
                int col = ncol0 + nf * 8 + t2;
                float2 bb = *reinterpret_cast<const float2*>(&bias[col]);
                float2 v0 = make_float2(acc[mt][nf][0] + bb.x, acc[mt][nf][1] + bb.y);
                float2 v1 = make_float2(acc[mt][nf][2] + bb.x, acc[mt][nf][3] + bb.y);
                *reinterpret_cast<float2*>(&d_Gib[(size_t)row * 256 + col]) = v0;
                *reinterpret_cast<float2*>(&d_Gib[(size_t)(row + 8) * 256 + col]) = v1;
            }
        }
    } else {
        int ncol0 = n0 + wn * 32;
#pragma unroll
        for (int mt = 0; mt < 2; mt++) {
#pragma unroll
            for (int nf = 0; nf < 4; nf++) {
                int row = m0 + wm * 32 + mt * 16 + g;
                int col = ncol0 + nf * 8 + t2;
                __half2 h0 = __floats2half2_rn(acc[mt][nf][0], acc[mt][nf][1]);
                __half2 h1 = __floats2half2_rn(acc[mt][nf][2], acc[mt][nf][3]);
                *reinterpret_cast<__half2*>(&d_Gj16[(size_t)row * 256 + col]) = h0;
                *reinterpret_cast<__half2*>(&d_Gj16[(size_t)(row + 8) * 256 + col]) = h1;
            }
        }
    }
}

// ---------------- edge phase (fp16 Gj, half2 lanes) ----------------
__global__ void edge_max_kernel(float* __restrict__ out, int layerOff, int writeNext) {
    int n = blockIdx.x;
    int t = threadIdx.x;                  // 0..127 (half2 lanes)
    int beg = d_rowptr[n], end = d_rowptr[n + 1];
    const __half ninf = __ushort_as_half((unsigned short)0xFC00);
    __half2 acc0 = __half2half2(ninf);    // (-inf, -inf)
    __half2 acc1 = acc0;
    int e = beg;
    for (; e + 2 <= end; e += 2) {
        int s0 = __ldg(&d_ssrc[e]);
        int s1 = __ldg(&d_ssrc[e + 1]);
        __half2 v0 = *reinterpret_cast<const __half2*>(&d_Gj16[(size_t)s0 * 256 + t * 2]);
        __half2 v1 = *reinterpret_cast<const __half2*>(&d_Gj16[(size_t)s1 * 256 + t * 2]);
        acc0 = __hmax2(acc0, v0);
        acc1 = __hmax2(acc1, v1);
    }
    if (e < end) {
        int s = __ldg(&d_ssrc[e]);
        __half2 v = *reinterpret_cast<const __half2*>(&d_Gj16[(size_t)s * 256 + t * 2]);
        acc0 = __hmax2(acc0, v);
    }
    float2 g = __half22float2(__hmax2(acc0, acc1));
    float2 gib = *reinterpret_cast<const float2*>(&d_Gib[(size_t)n * 256 + t * 2]);
    float r0 = fmaxf(g.x + gib.x, 0.f);   // empty segment: -inf -> relu -> 0
    float r1 = fmaxf(g.y + gib.y, 0.f);
    *reinterpret_cast<float2*>(&out[(size_t)n * OUTW + layerOff + t * 2]) = make_float2(r0, r1);
    if (writeNext) {
        __half2 h01 = __floats2half2_rn(r0, r1);
        reinterpret_cast<uint32_t*>(d_A16)[n * 128 + t] = *reinterpret_cast<uint32_t*>(&h01);
    }
}

// ---------------- launch ----------------
extern "C" void kernel_launch(void* const* d_in, const int* in_sizes, int n_in,
                              void* d_out, int out_size) {
    const float* x  = (const float*)d_in[0];
    const int*   ei = (const int*)  d_in[1];
    const float* W1 = (const float*)d_in[2];
    const float* b1 = (const float*)d_in[3];
    const float* W2 = (const float*)d_in[4];
    const float* b2 = (const float*)d_in[5];
    const float* W3 = (const float*)d_in[6];
    const float* b3 = (const float*)d_in[7];
    float* out = (float*)d_out;

    const int* src = ei;            // edge_index[0]
    const int* dst = ei + NEDGE;    // edge_index[1]

    static cudaStream_t s_side = nullptr;
    static cudaEvent_t  evF = nullptr, evJ = nullptr;
    static void* cntAddr = nullptr;
    if (!s_side) {                  // created on first (non-captured) correctness call
        cudaStreamCreateWithFlags(&s_side, cudaStreamNonBlocking);
        cudaEventCreateWithFlags(&evF, cudaEventDisableTiming);
        cudaEventCreateWithFlags(&evJ, cudaEventDisableTiming);
        cudaGetSymbolAddress(&cntAddr, d_cnt);
        cudaFuncSetAttribute(gemm_mma_kernel, cudaFuncAttributeMaxDynamicSharedMemorySize, SMEM_TOT);
    }

    // zero cnt (memset node), then merged setup (copyx+conv | prep_w | hist)
    cudaMemsetAsync(cntAddr, 0, NODES * sizeof(int), 0);
    setup_kernel<<<256, 256>>>(x, out, W1, W2, W3, dst);

    cudaEventRecord(evF, 0);
    gemm_mma_kernel<<<dim3(4, 32), 512, SMEM_TOT>>>(0, b1);

    // CSR tail (scan + scatter) on side stream, hidden under gemm0
    cudaStreamWaitEvent(s_side, evF, 0);
    scan_kernel<<<1, 1024, 0, s_side>>>();
    scatter_kernel<<<NEDGE / 256, 256, 0, s_side>>>(src, dst);
    cudaEventRecord(evJ, s_side);
    cudaStreamWaitEvent(0, evJ, 0);

    edge_max_kernel<<<NODES, 128>>>(out, 256, 1);
    gemm_mma_kernel<<<dim3(4, 32), 512, SMEM_TOT>>>(1, b2);
    edge_max_kernel<<<NODES, 128>>>(out, 512, 1);
    gemm_mma_kernel<<<dim3(4, 32), 512, SMEM_TOT>>>(2, b3);
    edge_max_kernel<<<NODES, 128>>>(out, 768, 0);
}